// round 3
// baseline (speedup 1.0000x reference)
#include <cuda_runtime.h>
#include <math.h>

// Problem constants (fixed by the reference)
#define BATCH 8
#define CH    512
#define HW    1024       // 32*32 spatial
#define NG    32         // num groups
#define CPG   16         // channels per group (512/32)
#define GRP_ELEMS (CPG*HW)   // 16384

// ---------------- scratch (static device globals; no allocation) -------------
__device__ float g_xn  [BATCH * CH * HW];        // 16.8 MB
__device__ float g_qkv [BATCH * 3 * CH * HW];    // 50.3 MB
__device__ float g_attn[BATCH * HW * HW];        // 33.5 MB
__device__ float g_out [BATCH * CH * HW];        // 16.8 MB

// ---------------- GroupNorm ---------------------------------------------------
// one block per (batch, group): reduce 16 channels x 1024 pixels
__global__ void groupnorm_kernel(const float* __restrict__ x,
                                 const float* __restrict__ w,
                                 const float* __restrict__ bias,
                                 float* __restrict__ xn)
{
    const int bg = blockIdx.x;        // 0..255
    const int b  = bg / NG;
    const int g  = bg % NG;
    const float* xp  = x  + ((size_t)b * CH + (size_t)g * CPG) * HW;
    float*       xnp = xn + ((size_t)b * CH + (size_t)g * CPG) * HW;

    float sum = 0.f, sq = 0.f;
    for (int i = threadIdx.x; i < GRP_ELEMS; i += blockDim.x) {
        float v = xp[i];
        sum += v;
        sq  += v * v;
    }
    // block reduction (warp shuffle + smem)
    __shared__ float ssum[32], ssq[32];
    int lane = threadIdx.x & 31, wid = threadIdx.x >> 5;
    #pragma unroll
    for (int o = 16; o > 0; o >>= 1) {
        sum += __shfl_xor_sync(0xffffffffu, sum, o);
        sq  += __shfl_xor_sync(0xffffffffu, sq,  o);
    }
    if (lane == 0) { ssum[wid] = sum; ssq[wid] = sq; }
    __syncthreads();
    int nw = blockDim.x >> 5;
    if (wid == 0) {
        sum = (lane < nw) ? ssum[lane] : 0.f;
        sq  = (lane < nw) ? ssq [lane] : 0.f;
        #pragma unroll
        for (int o = 16; o > 0; o >>= 1) {
            sum += __shfl_xor_sync(0xffffffffu, sum, o);
            sq  += __shfl_xor_sync(0xffffffffu, sq,  o);
        }
        if (lane == 0) { ssum[0] = sum; ssq[0] = sq; }
    }
    __syncthreads();
    const float inv_n = 1.f / (float)GRP_ELEMS;
    const float mean  = ssum[0] * inv_n;
    const float var   = ssq[0] * inv_n - mean * mean;
    const float rstd  = rsqrtf(var + 1e-5f);

    for (int i = threadIdx.x; i < GRP_ELEMS; i += blockDim.x) {
        int ch = g * CPG + (i >> 10);   // i / HW
        xnp[i] = (xp[i] - mean) * rstd * w[ch] + bias[ch];
    }
}

// ---------------- Tiled SGEMM -------------------------------------------------
// C[b][m][n] = alpha * sum_k A(m,k) * B(k,n)  (+ bias[m]) (+ res[b][m][n])
// TA: A stored as [K x M] row-major (A[k*lda+m]), else [M x K] (A[m*lda+k])
// TB: B stored as [N x K] row-major (B[n*ldb+k]), else [K x N] (B[k*ldb+n])
// All dims divisible by tile sizes for this problem; no bounds checks.
template<bool TA, bool TB, bool HAS_BIAS, bool HAS_RES>
__global__ __launch_bounds__(256)
void gemm_kernel(const float* __restrict__ A, const float* __restrict__ B,
                 const float* __restrict__ bias, const float* __restrict__ res,
                 float* __restrict__ Cp,
                 int M, int N, int K, int lda, int ldb,
                 size_t strideA, size_t strideB, size_t strideC, size_t strideRes,
                 float alpha)
{
    constexpr int BM = 64, BN = 64, BK = 16;
    __shared__ float As[BK][BM];
    __shared__ float Bs[BK][BN];

    const int batch = blockIdx.z;
    const int m0 = blockIdx.y * BM;
    const int n0 = blockIdx.x * BN;
    const int tid = threadIdx.x;
    const int tr = tid >> 4;          // 0..15 -> row group of 4
    const int tc = tid & 15;          // 0..15 -> col group of 4

    const float* Ab = A + batch * strideA;
    const float* Bb = B + batch * strideB;

    float acc[4][4];
    #pragma unroll
    for (int i = 0; i < 4; i++)
        #pragma unroll
        for (int j = 0; j < 4; j++) acc[i][j] = 0.f;

    for (int k0 = 0; k0 < K; k0 += BK) {
        // load A tile (BM*BK = 1024 elems, 4 per thread)
        #pragma unroll
        for (int e = tid; e < BM * BK; e += 256) {
            if (TA) { int k = e >> 6, m = e & 63;  As[k][m] = Ab[(size_t)(k0 + k) * lda + (m0 + m)]; }
            else    { int m = e >> 4, k = e & 15;  As[k][m] = Ab[(size_t)(m0 + m) * lda + (k0 + k)]; }
        }
        // load B tile
        #pragma unroll
        for (int e = tid; e < BN * BK; e += 256) {
            if (TB) { int n = e >> 4, k = e & 15;  Bs[k][n] = Bb[(size_t)(n0 + n) * ldb + (k0 + k)]; }
            else    { int k = e >> 6, n = e & 63;  Bs[k][n] = Bb[(size_t)(k0 + k) * ldb + (n0 + n)]; }
        }
        __syncthreads();

        #pragma unroll
        for (int k = 0; k < BK; k++) {
            float a[4], bb[4];
            *(float4*)a  = *(const float4*)&As[k][tr * 4];
            *(float4*)bb = *(const float4*)&Bs[k][tc * 4];
            #pragma unroll
            for (int i = 0; i < 4; i++)
                #pragma unroll
                for (int j = 0; j < 4; j++)
                    acc[i][j] = fmaf(a[i], bb[j], acc[i][j]);
        }
        __syncthreads();
    }

    float* Cb = Cp + batch * strideC;
    const float* Rb = HAS_RES ? (res + batch * strideRes) : nullptr;
    #pragma unroll
    for (int i = 0; i < 4; i++) {
        int m = m0 + tr * 4 + i;
        float bi = HAS_BIAS ? bias[m] : 0.f;
        #pragma unroll
        for (int j = 0; j < 4; j++) {
            int n = n0 + tc * 4 + j;
            float v = alpha * acc[i][j] + bi;
            if (HAS_RES) v += Rb[(size_t)m * N + n];
            Cb[(size_t)m * N + n] = v;
        }
    }
}

// ---------------- Row softmax (in place) -------------------------------------
// one block per row of 1024
__global__ __launch_bounds__(256)
void softmax_kernel(float* __restrict__ attn)
{
    float* row = attn + (size_t)blockIdx.x * HW;
    const int tid = threadIdx.x;
    float4 v = ((const float4*)row)[tid];

    float mx = fmaxf(fmaxf(v.x, v.y), fmaxf(v.z, v.w));
    __shared__ float sred[32];
    int lane = tid & 31, wid = tid >> 5;
    #pragma unroll
    for (int o = 16; o > 0; o >>= 1) mx = fmaxf(mx, __shfl_xor_sync(0xffffffffu, mx, o));
    if (lane == 0) sred[wid] = mx;
    __syncthreads();
    if (wid == 0) {
        mx = sred[lane & 7];
        #pragma unroll
        for (int o = 4; o > 0; o >>= 1) mx = fmaxf(mx, __shfl_xor_sync(0xffffffffu, mx, o));
        if (lane == 0) sred[0] = mx;
    }
    __syncthreads();
    mx = sred[0];

    v.x = __expf(v.x - mx); v.y = __expf(v.y - mx);
    v.z = __expf(v.z - mx); v.w = __expf(v.w - mx);
    float sum = v.x + v.y + v.z + v.w;
    #pragma unroll
    for (int o = 16; o > 0; o >>= 1) sum += __shfl_xor_sync(0xffffffffu, sum, o);
    if (lane == 0) sred[wid] = sum;
    __syncthreads();
    if (wid == 0) {
        sum = sred[lane & 7];
        #pragma unroll
        for (int o = 4; o > 0; o >>= 1) sum += __shfl_xor_sync(0xffffffffu, sum, o);
        if (lane == 0) sred[0] = sum;
    }
    __syncthreads();
    float inv = 1.f / sred[0];
    v.x *= inv; v.y *= inv; v.z *= inv; v.w *= inv;
    ((float4*)row)[tid] = v;
}

// ---------------- launch ------------------------------------------------------
extern "C" void kernel_launch(void* const* d_in, const int* in_sizes, int n_in,
                              void* d_out, int out_size)
{
    const float* x      = (const float*)d_in[0];
    const float* gn_w   = (const float*)d_in[1];
    const float* gn_b   = (const float*)d_in[2];
    const float* qkv_w  = (const float*)d_in[3];
    const float* qkv_b  = (const float*)d_in[4];
    const float* proj_w = (const float*)d_in[5];
    const float* proj_b = (const float*)d_in[6];
    float* out = (float*)d_out;

    float *xn, *qkv, *attn, *aout;
    cudaGetSymbolAddress((void**)&xn,   g_xn);
    cudaGetSymbolAddress((void**)&qkv,  g_qkv);
    cudaGetSymbolAddress((void**)&attn, g_attn);
    cudaGetSymbolAddress((void**)&aout, g_out);

    const size_t sX   = (size_t)CH * HW;        // per-batch stride of x/xn/out
    const size_t sQKV = (size_t)3 * CH * HW;
    const size_t sATT = (size_t)HW * HW;
    const float scale = rsqrtf((float)CH);      // 512^-0.5

    // 1) GroupNorm
    groupnorm_kernel<<<BATCH * NG, 256>>>(x, gn_w, gn_b, xn);

    // 2) QKV = W(1536x512) @ xn(512x1024) + b     [NN, bias]
    {
        dim3 grid(HW / 64, (3 * CH) / 64, BATCH);
        gemm_kernel<false, false, true, false><<<grid, 256>>>(
            qkv_w, xn, qkv_b, nullptr, qkv,
            3 * CH, HW, CH, CH, HW,
            0, sX, sQKV, 0, 1.0f);
    }

    // 3) scores = q^T k * scale                    [TN, alpha]
    {
        dim3 grid(HW / 64, HW / 64, BATCH);
        gemm_kernel<true, false, false, false><<<grid, 256>>>(
            qkv /*q*/, qkv + (size_t)CH * HW /*k*/, nullptr, nullptr, attn,
            HW, HW, CH, HW, HW,
            sQKV, sQKV, sATT, 0, scale);
    }

    // 4) softmax over last dim
    softmax_kernel<<<BATCH * HW, 256>>>(attn);

    // 5) out = v(512x1024) @ attn^T(1024x1024)     [NT]
    {
        dim3 grid(HW / 64, CH / 64, BATCH);
        gemm_kernel<false, true, false, false><<<grid, 256>>>(
            qkv + (size_t)2 * CH * HW /*v*/, attn, nullptr, nullptr, aout,
            CH, HW, HW, HW, HW,
            sQKV, sATT, sX, 0, 1.0f);
    }

    // 6) final = proj_w @ out + proj_b + x  -> d_out   [NN, bias, residual]
    {
        dim3 grid(HW / 64, CH / 64, BATCH);
        gemm_kernel<false, false, true, true><<<grid, 256>>>(
            proj_w, aout, proj_b, x, out,
            CH, HW, CH, CH, HW,
            0, sX, sX, sX, 1.0f);
    }
}

// round 4
// speedup vs baseline: 3.0941x; 3.0941x over previous
#include <cuda_runtime.h>
#include <stdint.h>
#include <math.h>

// Problem constants (fixed by the reference)
#define BATCH 8
#define CH    512
#define HW    1024       // 32*32 spatial
#define NG    32         // num groups
#define CPG   16         // channels per group (512/32)
#define GRP_ELEMS (CPG*HW)   // 16384

// ---------------- scratch (static device globals; no allocation) -------------
__device__ float g_xn  [BATCH * CH * HW];        // 16.8 MB
__device__ float g_qkv [BATCH * 3 * CH * HW];    // 50.3 MB
__device__ float g_attn[BATCH * HW * HW];        // 33.5 MB
__device__ float g_out [BATCH * CH * HW];        // 16.8 MB

// ---------------- GroupNorm ---------------------------------------------------
__global__ void groupnorm_kernel(const float* __restrict__ x,
                                 const float* __restrict__ w,
                                 const float* __restrict__ bias,
                                 float* __restrict__ xn)
{
    const int bg = blockIdx.x;        // 0..255
    const int b  = bg / NG;
    const int g  = bg % NG;
    const float* xp  = x  + ((size_t)b * CH + (size_t)g * CPG) * HW;
    float*       xnp = xn + ((size_t)b * CH + (size_t)g * CPG) * HW;

    float sum = 0.f, sq = 0.f;
    for (int i = threadIdx.x; i < GRP_ELEMS; i += blockDim.x) {
        float v = xp[i];
        sum += v;
        sq  += v * v;
    }
    __shared__ float ssum[32], ssq[32];
    int lane = threadIdx.x & 31, wid = threadIdx.x >> 5;
    #pragma unroll
    for (int o = 16; o > 0; o >>= 1) {
        sum += __shfl_xor_sync(0xffffffffu, sum, o);
        sq  += __shfl_xor_sync(0xffffffffu, sq,  o);
    }
    if (lane == 0) { ssum[wid] = sum; ssq[wid] = sq; }
    __syncthreads();
    int nw = blockDim.x >> 5;
    if (wid == 0) {
        sum = (lane < nw) ? ssum[lane] : 0.f;
        sq  = (lane < nw) ? ssq [lane] : 0.f;
        #pragma unroll
        for (int o = 16; o > 0; o >>= 1) {
            sum += __shfl_xor_sync(0xffffffffu, sum, o);
            sq  += __shfl_xor_sync(0xffffffffu, sq,  o);
        }
        if (lane == 0) { ssum[0] = sum; ssq[0] = sq; }
    }
    __syncthreads();
    const float inv_n = 1.f / (float)GRP_ELEMS;
    const float mean  = ssum[0] * inv_n;
    const float var   = ssq[0] * inv_n - mean * mean;
    const float rstd  = rsqrtf(var + 1e-5f);

    for (int i = threadIdx.x; i < GRP_ELEMS; i += blockDim.x) {
        int ch = g * CPG + (i >> 10);   // i / HW
        xnp[i] = (xp[i] - mean) * rstd * w[ch] + bias[ch];
    }
}

// ---------------- tf32 helpers ------------------------------------------------
__device__ __forceinline__ uint32_t f2tf32(float x) {
    uint32_t r;
    asm("cvt.rna.tf32.f32 %0, %1;" : "=r"(r) : "f"(x));
    return r;
}

// ---------------- tf32 tensor-core GEMM --------------------------------------
// C[b][m][n] = alpha * sum_k A(m,k) * B(k,n)  (+ bias[m]) (+ res[b][m][n])
// TA: A stored [K x M] (A[k*lda+m]); else [M x K] (A[m*lda+k])
// TB: B stored [N x K] (B[n*ldb+k]); else [K x N] (B[k*ldb+n])
// Tiles: BM=BN=128, BK=16. 256 threads = 8 warps in 2(M) x 4(N) grid,
// warp tile 64x32 via 4x4 grid of m16n8k8 tf32 MMAs. All dims divide tiles.
template<bool TA, bool TB, bool HAS_BIAS, bool HAS_RES>
__global__ __launch_bounds__(256)
void gemm_tf32(const float* __restrict__ A, const float* __restrict__ B,
               const float* __restrict__ bias, const float* __restrict__ res,
               float* __restrict__ Cp,
               int M, int N, int K, int lda, int ldb,
               size_t strideA, size_t strideB, size_t strideC, size_t strideRes,
               float alpha)
{
    constexpr int BM = 128, BN = 128, BK = 16, PAD = 4;
    __shared__ uint32_t As[BK][BM + PAD];
    __shared__ uint32_t Bs[BK][BN + PAD];

    const int tid  = threadIdx.x;
    const int lane = tid & 31;
    const int warp = tid >> 5;
    const int wm = warp & 1;      // 0..1 along M
    const int wn = warp >> 1;     // 0..3 along N
    const int g  = lane >> 2;     // group id 0..7
    const int tg = lane & 3;      // thread-in-group 0..3

    const int batch = blockIdx.z;
    const int m0 = blockIdx.y * BM;
    const int n0 = blockIdx.x * BN;

    const float* Ab = A + batch * strideA;
    const float* Bb = B + batch * strideB;

    float acc[4][4][4];
    #pragma unroll
    for (int i = 0; i < 4; i++)
        #pragma unroll
        for (int j = 0; j < 4; j++)
            #pragma unroll
            for (int r = 0; r < 4; r++) acc[i][j][r] = 0.f;

    for (int k0 = 0; k0 < K; k0 += BK) {
        // ---- stage A tile into As[k][m] (k-major)
        if (TA) {
            #pragma unroll
            for (int i = 0; i < 2; i++) {
                int idx = tid + i * 256;          // 0..511 float4 slots
                int k = idx >> 5, mq = idx & 31;  // m = mq*4
                float4 v = *(const float4*)&Ab[(size_t)(k0 + k) * lda + m0 + mq * 4];
                uint4 t = make_uint4(f2tf32(v.x), f2tf32(v.y), f2tf32(v.z), f2tf32(v.w));
                *(uint4*)&As[k][mq * 4] = t;
            }
        } else {
            #pragma unroll
            for (int i = 0; i < 2; i++) {
                int idx = tid + i * 256;
                int m = idx >> 2, kq = idx & 3;   // k = kq*4
                float4 v = *(const float4*)&Ab[(size_t)(m0 + m) * lda + k0 + kq * 4];
                As[kq * 4 + 0][m] = f2tf32(v.x);
                As[kq * 4 + 1][m] = f2tf32(v.y);
                As[kq * 4 + 2][m] = f2tf32(v.z);
                As[kq * 4 + 3][m] = f2tf32(v.w);
            }
        }
        // ---- stage B tile into Bs[k][n] (k-major)
        if (TB) {
            #pragma unroll
            for (int i = 0; i < 2; i++) {
                int idx = tid + i * 256;
                int n = idx >> 2, kq = idx & 3;
                float4 v = *(const float4*)&Bb[(size_t)(n0 + n) * ldb + k0 + kq * 4];
                Bs[kq * 4 + 0][n] = f2tf32(v.x);
                Bs[kq * 4 + 1][n] = f2tf32(v.y);
                Bs[kq * 4 + 2][n] = f2tf32(v.z);
                Bs[kq * 4 + 3][n] = f2tf32(v.w);
            }
        } else {
            #pragma unroll
            for (int i = 0; i < 2; i++) {
                int idx = tid + i * 256;
                int k = idx >> 5, nq = idx & 31;
                float4 v = *(const float4*)&Bb[(size_t)(k0 + k) * ldb + n0 + nq * 4];
                uint4 t = make_uint4(f2tf32(v.x), f2tf32(v.y), f2tf32(v.z), f2tf32(v.w));
                *(uint4*)&Bs[k][nq * 4] = t;
            }
        }
        __syncthreads();

        // ---- two k-steps of 8
        #pragma unroll
        for (int ks = 0; ks < 2; ks++) {
            const int kb = ks * 8;
            uint32_t af[4][4], bf[4][2];
            #pragma unroll
            for (int mt = 0; mt < 4; mt++) {
                int mb = wm * 64 + mt * 16;
                af[mt][0] = As[kb + tg    ][mb + g    ];
                af[mt][1] = As[kb + tg    ][mb + g + 8];
                af[mt][2] = As[kb + tg + 4][mb + g    ];
                af[mt][3] = As[kb + tg + 4][mb + g + 8];
            }
            #pragma unroll
            for (int nt = 0; nt < 4; nt++) {
                int nb = wn * 32 + nt * 8;
                bf[nt][0] = Bs[kb + tg    ][nb + g];
                bf[nt][1] = Bs[kb + tg + 4][nb + g];
            }
            #pragma unroll
            for (int mt = 0; mt < 4; mt++)
                #pragma unroll
                for (int nt = 0; nt < 4; nt++) {
                    asm volatile(
                        "mma.sync.aligned.m16n8k8.row.col.f32.tf32.tf32.f32 "
                        "{%0,%1,%2,%3}, {%4,%5,%6,%7}, {%8,%9}, {%0,%1,%2,%3};\n"
                        : "+f"(acc[mt][nt][0]), "+f"(acc[mt][nt][1]),
                          "+f"(acc[mt][nt][2]), "+f"(acc[mt][nt][3])
                        : "r"(af[mt][0]), "r"(af[mt][1]),
                          "r"(af[mt][2]), "r"(af[mt][3]),
                          "r"(bf[nt][0]), "r"(bf[nt][1]));
                }
        }
        __syncthreads();
    }

    // ---- epilogue
    float* Cb = Cp + batch * strideC;
    const float* Rb = HAS_RES ? (res + batch * strideRes) : nullptr;
    #pragma unroll
    for (int mt = 0; mt < 4; mt++) {
        int row = m0 + wm * 64 + mt * 16 + g;
        float bi0 = HAS_BIAS ? bias[row]     : 0.f;
        float bi1 = HAS_BIAS ? bias[row + 8] : 0.f;
        #pragma unroll
        for (int nt = 0; nt < 4; nt++) {
            int col = n0 + wn * 32 + nt * 8 + tg * 2;
            float2 v0, v1;
            v0.x = alpha * acc[mt][nt][0] + bi0;
            v0.y = alpha * acc[mt][nt][1] + bi0;
            v1.x = alpha * acc[mt][nt][2] + bi1;
            v1.y = alpha * acc[mt][nt][3] + bi1;
            if (HAS_RES) {
                float2 r0 = *(const float2*)&Rb[(size_t)row * N + col];
                float2 r1 = *(const float2*)&Rb[(size_t)(row + 8) * N + col];
                v0.x += r0.x; v0.y += r0.y;
                v1.x += r1.x; v1.y += r1.y;
            }
            *(float2*)&Cb[(size_t)row * N + col]       = v0;
            *(float2*)&Cb[(size_t)(row + 8) * N + col] = v1;
        }
    }
}

// ---------------- Row softmax (in place) -------------------------------------
__global__ __launch_bounds__(256)
void softmax_kernel(float* __restrict__ attn)
{
    float* row = attn + (size_t)blockIdx.x * HW;
    const int tid = threadIdx.x;
    float4 v = ((const float4*)row)[tid];

    float mx = fmaxf(fmaxf(v.x, v.y), fmaxf(v.z, v.w));
    __shared__ float sred[32];
    int lane = tid & 31, wid = tid >> 5;
    #pragma unroll
    for (int o = 16; o > 0; o >>= 1) mx = fmaxf(mx, __shfl_xor_sync(0xffffffffu, mx, o));
    if (lane == 0) sred[wid] = mx;
    __syncthreads();
    if (wid == 0) {
        mx = sred[lane & 7];
        #pragma unroll
        for (int o = 4; o > 0; o >>= 1) mx = fmaxf(mx, __shfl_xor_sync(0xffffffffu, mx, o));
        if (lane == 0) sred[0] = mx;
    }
    __syncthreads();
    mx = sred[0];

    v.x = __expf(v.x - mx); v.y = __expf(v.y - mx);
    v.z = __expf(v.z - mx); v.w = __expf(v.w - mx);
    float sum = v.x + v.y + v.z + v.w;
    #pragma unroll
    for (int o = 16; o > 0; o >>= 1) sum += __shfl_xor_sync(0xffffffffu, sum, o);
    if (lane == 0) sred[wid] = sum;
    __syncthreads();
    if (wid == 0) {
        sum = sred[lane & 7];
        #pragma unroll
        for (int o = 4; o > 0; o >>= 1) sum += __shfl_xor_sync(0xffffffffu, sum, o);
        if (lane == 0) sred[0] = sum;
    }
    __syncthreads();
    float inv = 1.f / sred[0];
    v.x *= inv; v.y *= inv; v.z *= inv; v.w *= inv;
    ((float4*)row)[tid] = v;
}

// ---------------- launch ------------------------------------------------------
extern "C" void kernel_launch(void* const* d_in, const int* in_sizes, int n_in,
                              void* d_out, int out_size)
{
    const float* x      = (const float*)d_in[0];
    const float* gn_w   = (const float*)d_in[1];
    const float* gn_b   = (const float*)d_in[2];
    const float* qkv_w  = (const float*)d_in[3];
    const float* qkv_b  = (const float*)d_in[4];
    const float* proj_w = (const float*)d_in[5];
    const float* proj_b = (const float*)d_in[6];
    float* out = (float*)d_out;

    float *xn, *qkv, *attn, *aout;
    cudaGetSymbolAddress((void**)&xn,   g_xn);
    cudaGetSymbolAddress((void**)&qkv,  g_qkv);
    cudaGetSymbolAddress((void**)&attn, g_attn);
    cudaGetSymbolAddress((void**)&aout, g_out);

    const size_t sX   = (size_t)CH * HW;
    const size_t sQKV = (size_t)3 * CH * HW;
    const size_t sATT = (size_t)HW * HW;
    const float scale = rsqrtf((float)CH);

    // 1) GroupNorm
    groupnorm_kernel<<<BATCH * NG, 256>>>(x, gn_w, gn_b, xn);

    // 2) QKV = W(1536x512) @ xn(512x1024) + b     [NN, bias]
    {
        dim3 grid(HW / 128, (3 * CH) / 128, BATCH);
        gemm_tf32<false, false, true, false><<<grid, 256>>>(
            qkv_w, xn, qkv_b, nullptr, qkv,
            3 * CH, HW, CH, CH, HW,
            0, sX, sQKV, 0, 1.0f);
    }

    // 3) scores = q^T k * scale                    [TN, alpha]
    {
        dim3 grid(HW / 128, HW / 128, BATCH);
        gemm_tf32<true, false, false, false><<<grid, 256>>>(
            qkv /*q*/, qkv + (size_t)CH * HW /*k*/, nullptr, nullptr, attn,
            HW, HW, CH, HW, HW,
            sQKV, sQKV, sATT, 0, scale);
    }

    // 4) softmax over last dim
    softmax_kernel<<<BATCH * HW, 256>>>(attn);

    // 5) out = v(512x1024) @ attn^T(1024x1024)     [NT]
    {
        dim3 grid(HW / 128, CH / 128, BATCH);
        gemm_tf32<false, true, false, false><<<grid, 256>>>(
            qkv + (size_t)2 * CH * HW /*v*/, attn, nullptr, nullptr, aout,
            CH, HW, HW, HW, HW,
            sQKV, sATT, sX, 0, 1.0f);
    }

    // 6) final = proj_w @ out + proj_b + x  -> d_out   [NN, bias, residual]
    {
        dim3 grid(HW / 128, CH / 128, BATCH);
        gemm_tf32<false, false, true, true><<<grid, 256>>>(
            proj_w, aout, proj_b, x, out,
            CH, HW, CH, CH, HW,
            0, sX, sX, sX, 1.0f);
    }
}

// round 5
// speedup vs baseline: 5.4784x; 1.7706x over previous
#include <cuda_runtime.h>
#include <cuda_bf16.h>
#include <stdint.h>
#include <math.h>

// Problem constants (fixed by the reference)
#define BATCH 8
#define CH    512
#define HW    1024       // 32*32 spatial
#define NG    32
#define CPG   16
#define GRP_ELEMS (CPG*HW)   // 16384

// ---------------- scratch (static device globals; no allocation) -------------
// All intermediates stored so every GEMM is TA=N (A row-major, k-contig)
// and TB=T (B row-major [n][k], k-contig): both smem stagings coalesce.
__device__ float g_xnT  [BATCH * HW * CH];   // xn transposed: [b][pixel][c]
__device__ float g_qT   [BATCH * HW * CH];   // Q^T: [b][i][c]
__device__ float g_kT   [BATCH * HW * CH];   // K^T: [b][j][c]
__device__ float g_v    [BATCH * CH * HW];   // V:   [b][c][j]
__device__ float g_attn [BATCH * HW * HW];   // [b][i][j]
__device__ float g_aoutT[BATCH * HW * CH];   // out^T: [b][i][c]

// ---------------- GroupNorm (writes transposed xnT via smem tile) ------------
__global__ __launch_bounds__(256)
void groupnorm_t_kernel(const float* __restrict__ x,
                        const float* __restrict__ w,
                        const float* __restrict__ bias,
                        float* __restrict__ xnT)
{
    const int bg = blockIdx.x;        // 0..255
    const int b  = bg / NG;
    const int g  = bg % NG;
    const float* xp = x + ((size_t)b * CH + (size_t)g * CPG) * HW;

    const int tid = threadIdx.x;
    float sum = 0.f, sq = 0.f;
    for (int i = tid; i < GRP_ELEMS; i += 256) {
        float v = xp[i];
        sum += v; sq += v * v;
    }
    __shared__ float ssum[8], ssq[8];
    int lane = tid & 31, wid = tid >> 5;
    #pragma unroll
    for (int o = 16; o > 0; o >>= 1) {
        sum += __shfl_xor_sync(0xffffffffu, sum, o);
        sq  += __shfl_xor_sync(0xffffffffu, sq,  o);
    }
    if (lane == 0) { ssum[wid] = sum; ssq[wid] = sq; }
    __syncthreads();
    if (wid == 0) {
        sum = ssum[lane & 7];
        sq  = ssq [lane & 7];
        #pragma unroll
        for (int o = 4; o > 0; o >>= 1) {
            sum += __shfl_xor_sync(0xffffffffu, sum, o);
            sq  += __shfl_xor_sync(0xffffffffu, sq,  o);
        }
        if (lane == 0) { ssum[0] = sum; ssq[0] = sq; }
    }
    __syncthreads();
    const float inv_n = 1.f / (float)GRP_ELEMS;
    const float mean  = ssum[0] * inv_n;
    const float var   = ssq[0] * inv_n - mean * mean;
    const float rstd  = rsqrtf(var + 1e-5f);

    __shared__ float tile[CPG][64 + 1];
    for (int pt = 0; pt < 16; pt++) {            // 16 tiles of 64 pixels
        __syncthreads();
        #pragma unroll
        for (int j = 0; j < 4; j++) {
            int e = tid + j * 256;               // 0..1023
            int c = e >> 6, p = e & 63;
            float v = xp[c * HW + pt * 64 + p];
            tile[c][p] = (v - mean) * rstd * w[g * CPG + c] + bias[g * CPG + c];
        }
        __syncthreads();
        int p = tid >> 2, cq = tid & 3;
        float4 o;
        o.x = tile[cq * 4 + 0][p];
        o.y = tile[cq * 4 + 1][p];
        o.z = tile[cq * 4 + 2][p];
        o.w = tile[cq * 4 + 3][p];
        *(float4*)&xnT[((size_t)b * HW + pt * 64 + p) * CH + g * CPG + cq * 4] = o;
    }
}

// ---------------- bf16 helpers ------------------------------------------------
__device__ __forceinline__ uint32_t packbf(float x, float y) {
    __nv_bfloat162 h = __float22bfloat162_rn(make_float2(x, y));
    return *(uint32_t*)&h;
}

// ---------------- bf16 tensor-core GEMM (TA=N, TB=T fixed) -------------------
// C[b][m][n] = alpha * sum_k A[m][k] * B[n][k]  (+biasM[m]) (+biasN[n]) (+res)
// A row-major [M x K] (lda), B row-major [N x K] (ldb), C row-major ldc=N.
// Tiles: BM=BN=128, BK=32. 256 threads = 8 warps (2M x 4N), warp tile 64x32,
// mma.m16n8k16.bf16. Register-staged pipeline hides global latency.
template<bool BIAS_M, bool BIAS_N, bool HAS_RES>
__global__ __launch_bounds__(256, 2)
void gemm_bf16(const float* __restrict__ A, const float* __restrict__ B,
               const float* __restrict__ biasM, const float* __restrict__ biasN,
               const float* __restrict__ res, float* __restrict__ Cp,
               int M, int N, int K, int lda, int ldb,
               size_t strideA, size_t strideB, size_t strideC, size_t strideRes,
               float alpha)
{
    constexpr int BM = 128, BN = 128, BK = 32, PAD = 4;
    __shared__ __nv_bfloat16 As[BM][BK + PAD];
    __shared__ __nv_bfloat16 Bs[BN][BK + PAD];

    const int tid  = threadIdx.x;
    const int lane = tid & 31;
    const int warp = tid >> 5;
    const int wm = warp & 1;      // 0..1 along M
    const int wn = warp >> 1;     // 0..3 along N
    const int g   = lane >> 2;    // 0..7
    const int tg2 = (lane & 3) * 2;

    const int batch = blockIdx.z;
    const int m0 = blockIdx.y * BM;
    const int n0 = blockIdx.x * BN;

    // staging thread map: float4 column kq (0..7), row base rb (0..31), 4 passes
    const int rb = tid >> 3;      // 0..31
    const int kq = tid & 7;       // 0..7

    const float* Ab = A + batch * strideA + (size_t)(m0 + rb) * lda + kq * 4;
    const float* Bb = B + batch * strideB + (size_t)(n0 + rb) * ldb + kq * 4;

    float acc[4][4][4];
    #pragma unroll
    for (int i = 0; i < 4; i++)
        #pragma unroll
        for (int j = 0; j < 4; j++)
            #pragma unroll
            for (int r = 0; r < 4; r++) acc[i][j][r] = 0.f;

    float4 rA[4], rB[4];
    // prologue load (k0 = 0)
    #pragma unroll
    for (int p = 0; p < 4; p++) {
        rA[p] = *(const float4*)&Ab[(size_t)(32 * p) * lda];
        rB[p] = *(const float4*)&Bb[(size_t)(32 * p) * ldb];
    }

    const int nk = K / BK;
    for (int kt = 0; kt < nk; kt++) {
        __syncthreads();
        // stage regs -> smem (convert to bf16)
        #pragma unroll
        for (int p = 0; p < 4; p++) {
            uint2 ua = make_uint2(packbf(rA[p].x, rA[p].y), packbf(rA[p].z, rA[p].w));
            uint2 ub = make_uint2(packbf(rB[p].x, rB[p].y), packbf(rB[p].z, rB[p].w));
            *(uint2*)&As[rb + 32 * p][kq * 4] = ua;
            *(uint2*)&Bs[rb + 32 * p][kq * 4] = ub;
        }
        __syncthreads();
        // prefetch next tile (consumed next iteration; overlaps with MMAs)
        if (kt + 1 < nk) {
            const float* An = Ab + (size_t)(kt + 1) * BK;
            const float* Bn = Bb + (size_t)(kt + 1) * BK;
            #pragma unroll
            for (int p = 0; p < 4; p++) {
                rA[p] = *(const float4*)&An[(size_t)(32 * p) * lda];
                rB[p] = *(const float4*)&Bn[(size_t)(32 * p) * ldb];
            }
        }
        // compute: 2 k-steps of 16
        #pragma unroll
        for (int ks = 0; ks < 2; ks++) {
            const int kb = ks * 16;
            uint32_t bf[4][2];
            #pragma unroll
            for (int nt = 0; nt < 4; nt++) {
                int nb = wn * 32 + nt * 8 + g;
                bf[nt][0] = *(const uint32_t*)&Bs[nb][kb + tg2];
                bf[nt][1] = *(const uint32_t*)&Bs[nb][kb + tg2 + 8];
            }
            #pragma unroll
            for (int mt = 0; mt < 4; mt++) {
                int mb = wm * 64 + mt * 16;
                uint32_t a0 = *(const uint32_t*)&As[mb + g    ][kb + tg2];
                uint32_t a1 = *(const uint32_t*)&As[mb + g + 8][kb + tg2];
                uint32_t a2 = *(const uint32_t*)&As[mb + g    ][kb + tg2 + 8];
                uint32_t a3 = *(const uint32_t*)&As[mb + g + 8][kb + tg2 + 8];
                #pragma unroll
                for (int nt = 0; nt < 4; nt++) {
                    asm volatile(
                        "mma.sync.aligned.m16n8k16.row.col.f32.bf16.bf16.f32 "
                        "{%0,%1,%2,%3}, {%4,%5,%6,%7}, {%8,%9}, {%0,%1,%2,%3};\n"
                        : "+f"(acc[mt][nt][0]), "+f"(acc[mt][nt][1]),
                          "+f"(acc[mt][nt][2]), "+f"(acc[mt][nt][3])
                        : "r"(a0), "r"(a1), "r"(a2), "r"(a3),
                          "r"(bf[nt][0]), "r"(bf[nt][1]));
                }
            }
        }
    }

    // ---- epilogue
    float* Cb = Cp + batch * strideC;
    const float* Rb = HAS_RES ? (res + batch * strideRes) : nullptr;
    #pragma unroll
    for (int mt = 0; mt < 4; mt++) {
        int row = m0 + wm * 64 + mt * 16 + g;
        float bm0 = BIAS_M ? biasM[row]     : 0.f;
        float bm1 = BIAS_M ? biasM[row + 8] : 0.f;
        #pragma unroll
        for (int nt = 0; nt < 4; nt++) {
            int col = n0 + wn * 32 + nt * 8 + tg2;
            float2 v0, v1;
            v0.x = alpha * acc[mt][nt][0] + bm0;
            v0.y = alpha * acc[mt][nt][1] + bm0;
            v1.x = alpha * acc[mt][nt][2] + bm1;
            v1.y = alpha * acc[mt][nt][3] + bm1;
            if (BIAS_N) {
                float2 bn = *(const float2*)&biasN[col];
                v0.x += bn.x; v0.y += bn.y;
                v1.x += bn.x; v1.y += bn.y;
            }
            if (HAS_RES) {
                float2 r0 = *(const float2*)&Rb[(size_t)row * N + col];
                float2 r1 = *(const float2*)&Rb[(size_t)(row + 8) * N + col];
                v0.x += r0.x; v0.y += r0.y;
                v1.x += r1.x; v1.y += r1.y;
            }
            *(float2*)&Cb[(size_t)row * N + col]       = v0;
            *(float2*)&Cb[(size_t)(row + 8) * N + col] = v1;
        }
    }
}

// ---------------- Row softmax (in place) -------------------------------------
__global__ __launch_bounds__(256)
void softmax_kernel(float* __restrict__ attn)
{
    float* row = attn + (size_t)blockIdx.x * HW;
    const int tid = threadIdx.x;
    float4 v = ((const float4*)row)[tid];

    float mx = fmaxf(fmaxf(v.x, v.y), fmaxf(v.z, v.w));
    __shared__ float sred[32];
    int lane = tid & 31, wid = tid >> 5;
    #pragma unroll
    for (int o = 16; o > 0; o >>= 1) mx = fmaxf(mx, __shfl_xor_sync(0xffffffffu, mx, o));
    if (lane == 0) sred[wid] = mx;
    __syncthreads();
    if (wid == 0) {
        mx = sred[lane & 7];
        #pragma unroll
        for (int o = 4; o > 0; o >>= 1) mx = fmaxf(mx, __shfl_xor_sync(0xffffffffu, mx, o));
        if (lane == 0) sred[0] = mx;
    }
    __syncthreads();
    mx = sred[0];

    v.x = __expf(v.x - mx); v.y = __expf(v.y - mx);
    v.z = __expf(v.z - mx); v.w = __expf(v.w - mx);
    float sum = v.x + v.y + v.z + v.w;
    #pragma unroll
    for (int o = 16; o > 0; o >>= 1) sum += __shfl_xor_sync(0xffffffffu, sum, o);
    if (lane == 0) sred[wid] = sum;
    __syncthreads();
    if (wid == 0) {
        sum = sred[lane & 7];
        #pragma unroll
        for (int o = 4; o > 0; o >>= 1) sum += __shfl_xor_sync(0xffffffffu, sum, o);
        if (lane == 0) sred[0] = sum;
    }
    __syncthreads();
    float inv = 1.f / sred[0];
    v.x *= inv; v.y *= inv; v.z *= inv; v.w *= inv;
    ((float4*)row)[tid] = v;
}

// ---------------- launch ------------------------------------------------------
extern "C" void kernel_launch(void* const* d_in, const int* in_sizes, int n_in,
                              void* d_out, int out_size)
{
    const float* x      = (const float*)d_in[0];
    const float* gn_w   = (const float*)d_in[1];
    const float* gn_b   = (const float*)d_in[2];
    const float* qkv_w  = (const float*)d_in[3];
    const float* qkv_b  = (const float*)d_in[4];
    const float* proj_w = (const float*)d_in[5];
    const float* proj_b = (const float*)d_in[6];
    float* out = (float*)d_out;

    float *xnT, *qT, *kT, *v, *attn, *aoutT;
    cudaGetSymbolAddress((void**)&xnT,   g_xnT);
    cudaGetSymbolAddress((void**)&qT,    g_qT);
    cudaGetSymbolAddress((void**)&kT,    g_kT);
    cudaGetSymbolAddress((void**)&v,     g_v);
    cudaGetSymbolAddress((void**)&attn,  g_attn);
    cudaGetSymbolAddress((void**)&aoutT, g_aoutT);

    const size_t sNC  = (size_t)HW * CH;   // stride of [pixel][c] tensors
    const size_t sCN  = (size_t)CH * HW;   // stride of [c][pixel] tensors
    const size_t sATT = (size_t)HW * HW;
    const float scale = rsqrtf((float)CH);

    // 1) GroupNorm -> xnT [b][pixel][c]
    groupnorm_t_kernel<<<BATCH * NG, 256>>>(x, gn_w, gn_b, xnT);

    // 2) QT[i][co] = sum_c xnT[i][c] * Wq[co][c] + qkv_b[co]      (bias on N)
    {
        dim3 grid(CH / 128, HW / 128, BATCH);
        gemm_bf16<false, true, false><<<grid, 256>>>(
            xnT, qkv_w, nullptr, qkv_b, nullptr, qT,
            HW, CH, CH, CH, CH, sNC, 0, sNC, 0, 1.0f);
    }
    // 3) KT[j][co] = sum_c xnT[j][c] * Wk[co][c] + qkv_b[CH+co]
    {
        dim3 grid(CH / 128, HW / 128, BATCH);
        gemm_bf16<false, true, false><<<grid, 256>>>(
            xnT, qkv_w + (size_t)CH * CH, nullptr, qkv_b + CH, nullptr, kT,
            HW, CH, CH, CH, CH, sNC, 0, sNC, 0, 1.0f);
    }
    // 4) V[co][j] = sum_c Wv[co][c] * xnT[j][c] + qkv_b[2CH+co]   (bias on M)
    {
        dim3 grid(HW / 128, CH / 128, BATCH);
        gemm_bf16<true, false, false><<<grid, 256>>>(
            qkv_w + (size_t)2 * CH * CH, xnT, qkv_b + 2 * CH, nullptr, nullptr, v,
            CH, HW, CH, CH, CH, 0, sNC, sCN, 0, 1.0f);
    }
    // 5) S[i][j] = scale * sum_c QT[i][c] * KT[j][c]
    {
        dim3 grid(HW / 128, HW / 128, BATCH);
        gemm_bf16<false, false, false><<<grid, 256>>>(
            qT, kT, nullptr, nullptr, nullptr, attn,
            HW, HW, CH, CH, CH, sNC, sNC, sATT, 0, scale);
    }
    // 6) softmax rows
    softmax_kernel<<<BATCH * HW, 256>>>(attn);

    // 7) aoutT[i][c] = sum_j attn[i][j] * V[c][j]
    {
        dim3 grid(CH / 128, HW / 128, BATCH);
        gemm_bf16<false, false, false><<<grid, 256>>>(
            attn, v, nullptr, nullptr, nullptr, aoutT,
            HW, CH, HW, HW, HW, sATT, sCN, sNC, 0, 1.0f);
    }
    // 8) out[co][pix] = sum_c P[co][c] * aoutT[pix][c] + proj_b[co] + x
    {
        dim3 grid(HW / 128, CH / 128, BATCH);
        gemm_bf16<true, false, true><<<grid, 256>>>(
            proj_w, aoutT, proj_b, nullptr, x, out,
            CH, HW, CH, CH, CH, 0, sNC, sCN, sCN, 1.0f);
    }
}

// round 6
// speedup vs baseline: 8.0878x; 1.4763x over previous
#include <cuda_runtime.h>
#include <cuda_bf16.h>
#include <stdint.h>
#include <math.h>

// Problem constants (fixed by the reference)
#define BATCH 8
#define CH    512
#define HW    1024       // 32*32 spatial
#define NG    32
#define CPG   16
#define GRP_ELEMS (CPG*HW)   // 16384

typedef __nv_bfloat16 bf16;

// ---------------- scratch (static device globals; no allocation) -------------
__device__ bf16  g_xnT   [BATCH * HW * CH];    // xn^T  [b][pix][c]   bf16
__device__ bf16  g_qT    [BATCH * HW * CH];    // Q^T   [b][i][c]
__device__ bf16  g_kT    [BATCH * HW * CH];    // K^T   [b][j][c]
__device__ bf16  g_v     [BATCH * CH * HW];    // V     [b][c][j]
__device__ float g_attn  [BATCH * HW * HW];    // scores fp32 [b][i][j]
__device__ bf16  g_attnbf[BATCH * HW * HW];    // softmaxed, bf16
__device__ bf16  g_aoutT [BATCH * HW * CH];    // out^T [b][i][c]
__device__ bf16  g_wbf   [3 * CH * CH];        // qkv_w bf16
__device__ bf16  g_pwbf  [CH * CH];            // proj_w bf16

// ---------------- helpers -----------------------------------------------------
__device__ __forceinline__ uint32_t packbf(float x, float y) {
    __nv_bfloat162 h = __float22bfloat162_rn(make_float2(x, y));
    return *(uint32_t*)&h;
}
__device__ __forceinline__ uint32_t smem_u32(const void* p) {
    return (uint32_t)__cvta_generic_to_shared(p);
}
#define CP_ASYNC16(dst, src) \
    asm volatile("cp.async.cg.shared.global [%0], [%1], 16;\n" :: "r"(dst), "l"(src))
#define CP_COMMIT()  asm volatile("cp.async.commit_group;\n" ::)
#define CP_WAIT1()   asm volatile("cp.async.wait_group 1;\n" ::)

// ---------------- weight conversion f32 -> bf16 ------------------------------
__global__ void tobf16_kernel(const float* __restrict__ in, bf16* __restrict__ out, int n4)
{
    int i = blockIdx.x * blockDim.x + threadIdx.x;
    if (i < n4) {
        float4 v = ((const float4*)in)[i];
        uint2 o = make_uint2(packbf(v.x, v.y), packbf(v.z, v.w));
        ((uint2*)out)[i] = o;
    }
}

// ---------------- GroupNorm (writes transposed bf16 xnT) ---------------------
__global__ __launch_bounds__(256)
void groupnorm_t_kernel(const float* __restrict__ x,
                        const float* __restrict__ w,
                        const float* __restrict__ bias,
                        bf16* __restrict__ xnT)
{
    const int bg = blockIdx.x;        // 0..255
    const int b  = bg / NG;
    const int g  = bg % NG;
    const float* xp = x + ((size_t)b * CH + (size_t)g * CPG) * HW;

    const int tid = threadIdx.x;
    float sum = 0.f, sq = 0.f;
    for (int i = tid; i < GRP_ELEMS; i += 256) {
        float v = xp[i];
        sum += v; sq += v * v;
    }
    __shared__ float ssum[8], ssq[8];
    int lane = tid & 31, wid = tid >> 5;
    #pragma unroll
    for (int o = 16; o > 0; o >>= 1) {
        sum += __shfl_xor_sync(0xffffffffu, sum, o);
        sq  += __shfl_xor_sync(0xffffffffu, sq,  o);
    }
    if (lane == 0) { ssum[wid] = sum; ssq[wid] = sq; }
    __syncthreads();
    if (wid == 0) {
        sum = ssum[lane & 7];
        sq  = ssq [lane & 7];
        #pragma unroll
        for (int o = 4; o > 0; o >>= 1) {
            sum += __shfl_xor_sync(0xffffffffu, sum, o);
            sq  += __shfl_xor_sync(0xffffffffu, sq,  o);
        }
        if (lane == 0) { ssum[0] = sum; ssq[0] = sq; }
    }
    __syncthreads();
    const float inv_n = 1.f / (float)GRP_ELEMS;
    const float mean  = ssum[0] * inv_n;
    const float var   = ssq[0] * inv_n - mean * mean;
    const float rstd  = rsqrtf(var + 1e-5f);

    __shared__ float tile[CPG][64 + 1];
    for (int pt = 0; pt < 16; pt++) {
        __syncthreads();
        #pragma unroll
        for (int j = 0; j < 4; j++) {
            int e = tid + j * 256;
            int c = e >> 6, p = e & 63;
            float v = xp[c * HW + pt * 64 + p];
            tile[c][p] = (v - mean) * rstd * w[g * CPG + c] + bias[g * CPG + c];
        }
        __syncthreads();
        int p = tid >> 2, cq = tid & 3;
        uint2 o = make_uint2(packbf(tile[cq * 4 + 0][p], tile[cq * 4 + 1][p]),
                             packbf(tile[cq * 4 + 2][p], tile[cq * 4 + 3][p]));
        *(uint2*)&xnT[((size_t)b * HW + pt * 64 + p) * CH + g * CPG + cq * 4] = o;
    }
}

// ---------------- pipelined bf16 tensor-core GEMM ----------------------------
// C[b][m][n] = alpha * sum_k A[m][k]*B[n][k]  (+biasM[m]) (+biasN[n]) (+res)
// A: bf16 [M x K] row-major (lda). B: bf16 [N x K] row-major (ldb).
// C: fp32 or bf16 (OUT_BF), row-major ldc=N. Tiles BM=BN=128, BK=32.
// 8 warps (2M x 4N), warp tile 64x32, mma.m16n8k16. cp.async double buffer +
// ldmatrix.x4 from pad-8 smem rows (80B stride: conflict-free LDSM).
template<bool BIAS_M, bool BIAS_N, bool HAS_RES, bool OUT_BF>
__global__ __launch_bounds__(256, 2)
void gemm_pipe(const bf16* __restrict__ A, const bf16* __restrict__ B,
               const float* __restrict__ biasM, const float* __restrict__ biasN,
               const float* __restrict__ res, void* __restrict__ Cp,
               int M, int N, int K, int lda, int ldb,
               size_t strideA, size_t strideB, size_t strideC, size_t strideRes,
               float alpha)
{
    constexpr int BM = 128, BK = 32, LDS = BK + 8;   // 40 elems = 80B row
    __shared__ bf16 As[2][BM][LDS];
    __shared__ bf16 Bs[2][BM][LDS];

    const int tid  = threadIdx.x;
    const int lane = tid & 31;
    const int warp = tid >> 5;
    const int wm = warp & 1;
    const int wn = warp >> 1;
    const int g   = lane >> 2;
    const int tg2 = (lane & 3) * 2;

    const int batch = blockIdx.z;
    const int m0 = blockIdx.y * BM;
    const int n0 = blockIdx.x * BM;

    // staging map: row = tid>>2 (0..63, +64 second pass), ch = tid&3 (16B chunk)
    const int srow = tid >> 2;
    const int sch  = tid & 3;
    const bf16* Ag = A + batch * strideA + (size_t)(m0 + srow) * lda + sch * 8;
    const bf16* Bg = B + batch * strideB + (size_t)(n0 + srow) * ldb + sch * 8;
    const uint32_t sA0 = smem_u32(&As[0][srow][sch * 8]);
    const uint32_t sB0 = smem_u32(&Bs[0][srow][sch * 8]);
    constexpr uint32_t STAGE = BM * LDS * 2;        // bytes per stage
    constexpr uint32_t R64   = 64 * LDS * 2;        // 64 rows of smem

    const int nk = K / BK;

    // prologue: stage 0 and 1
    #pragma unroll
    for (int s = 0; s < 2; s++) {
        const bf16* Ak = Ag + s * BK;
        const bf16* Bk = Bg + s * BK;
        CP_ASYNC16(sA0 + s * STAGE,       Ak);
        CP_ASYNC16(sA0 + s * STAGE + R64, Ak + (size_t)64 * lda);
        CP_ASYNC16(sB0 + s * STAGE,       Bk);
        CP_ASYNC16(sB0 + s * STAGE + R64, Bk + (size_t)64 * ldb);
        CP_COMMIT();
    }

    float acc[4][4][4];
    #pragma unroll
    for (int i = 0; i < 4; i++)
        #pragma unroll
        for (int j = 0; j < 4; j++)
            #pragma unroll
            for (int r = 0; r < 4; r++) acc[i][j][r] = 0.f;

    // lane-dependent ldmatrix row/col offsets
    const int arow = (lane & 15);                 // A: m offset within 16
    const int acol = ((lane >> 4) & 1) * 8;       // A: k offset 0/8
    const int brow = (lane & 7) + ((lane >> 4) << 3);  // B: n offset within 16
    const int bcol = ((lane >> 3) & 1) * 8;       // B: k offset 0/8

    for (int kt = 0; kt < nk; kt++) {
        CP_WAIT1();
        __syncthreads();
        const int buf = kt & 1;

        #pragma unroll
        for (int ks = 0; ks < 2; ks++) {
            const int kb = ks * 16;
            uint32_t a[4][4];
            #pragma unroll
            for (int mt = 0; mt < 4; mt++) {
                uint32_t addr = smem_u32(&As[buf][wm * 64 + mt * 16 + arow][kb + acol]);
                asm volatile("ldmatrix.sync.aligned.m8n8.x4.shared.b16 {%0,%1,%2,%3}, [%4];\n"
                             : "=r"(a[mt][0]), "=r"(a[mt][1]), "=r"(a[mt][2]), "=r"(a[mt][3])
                             : "r"(addr));
            }
            uint32_t b[4][2];
            #pragma unroll
            for (int np = 0; np < 2; np++) {
                uint32_t addr = smem_u32(&Bs[buf][wn * 32 + np * 16 + brow][kb + bcol]);
                uint32_t r0, r1, r2, r3;
                asm volatile("ldmatrix.sync.aligned.m8n8.x4.shared.b16 {%0,%1,%2,%3}, [%4];\n"
                             : "=r"(r0), "=r"(r1), "=r"(r2), "=r"(r3)
                             : "r"(addr));
                b[np * 2 + 0][0] = r0; b[np * 2 + 0][1] = r1;
                b[np * 2 + 1][0] = r2; b[np * 2 + 1][1] = r3;
            }
            #pragma unroll
            for (int mt = 0; mt < 4; mt++)
                #pragma unroll
                for (int nt = 0; nt < 4; nt++) {
                    asm volatile(
                        "mma.sync.aligned.m16n8k16.row.col.f32.bf16.bf16.f32 "
                        "{%0,%1,%2,%3}, {%4,%5,%6,%7}, {%8,%9}, {%0,%1,%2,%3};\n"
                        : "+f"(acc[mt][nt][0]), "+f"(acc[mt][nt][1]),
                          "+f"(acc[mt][nt][2]), "+f"(acc[mt][nt][3])
                        : "r"(a[mt][0]), "r"(a[mt][1]), "r"(a[mt][2]), "r"(a[mt][3]),
                          "r"(b[nt][0]), "r"(b[nt][1]));
                }
        }
        __syncthreads();
        const int kn = kt + 2;
        if (kn < nk) {
            const bf16* Ak = Ag + kn * BK;
            const bf16* Bk = Bg + kn * BK;
            CP_ASYNC16(sA0 + buf * STAGE,       Ak);
            CP_ASYNC16(sA0 + buf * STAGE + R64, Ak + (size_t)64 * lda);
            CP_ASYNC16(sB0 + buf * STAGE,       Bk);
            CP_ASYNC16(sB0 + buf * STAGE + R64, Bk + (size_t)64 * ldb);
        }
        CP_COMMIT();
    }

    // ---- epilogue
    const float* Rb = HAS_RES ? (res + batch * strideRes) : nullptr;
    #pragma unroll
    for (int mt = 0; mt < 4; mt++) {
        int row = m0 + wm * 64 + mt * 16 + g;
        float bm0 = BIAS_M ? biasM[row]     : 0.f;
        float bm1 = BIAS_M ? biasM[row + 8] : 0.f;
        #pragma unroll
        for (int nt = 0; nt < 4; nt++) {
            int col = n0 + wn * 32 + nt * 8 + tg2;
            float2 v0, v1;
            v0.x = alpha * acc[mt][nt][0] + bm0;
            v0.y = alpha * acc[mt][nt][1] + bm0;
            v1.x = alpha * acc[mt][nt][2] + bm1;
            v1.y = alpha * acc[mt][nt][3] + bm1;
            if (BIAS_N) {
                float2 bn = *(const float2*)&biasN[col];
                v0.x += bn.x; v0.y += bn.y;
                v1.x += bn.x; v1.y += bn.y;
            }
            if (HAS_RES) {
                float2 r0 = *(const float2*)&Rb[(size_t)row * N + col];
                float2 r1 = *(const float2*)&Rb[(size_t)(row + 8) * N + col];
                v0.x += r0.x; v0.y += r0.y;
                v1.x += r1.x; v1.y += r1.y;
            }
            if (OUT_BF) {
                bf16* Cb = (bf16*)Cp + batch * strideC;
                *(uint32_t*)&Cb[(size_t)row * N + col]       = packbf(v0.x, v0.y);
                *(uint32_t*)&Cb[(size_t)(row + 8) * N + col] = packbf(v1.x, v1.y);
            } else {
                float* Cb = (float*)Cp + batch * strideC;
                *(float2*)&Cb[(size_t)row * N + col]       = v0;
                *(float2*)&Cb[(size_t)(row + 8) * N + col] = v1;
            }
        }
    }
}

// ---------------- Row softmax: fp32 in -> bf16 out ---------------------------
__global__ __launch_bounds__(256)
void softmax_kernel(const float* __restrict__ attn, bf16* __restrict__ attnbf)
{
    const float* row = attn + (size_t)blockIdx.x * HW;
    bf16* orow = attnbf + (size_t)blockIdx.x * HW;
    const int tid = threadIdx.x;
    float4 v = ((const float4*)row)[tid];

    float mx = fmaxf(fmaxf(v.x, v.y), fmaxf(v.z, v.w));
    __shared__ float sred[8];
    int lane = tid & 31, wid = tid >> 5;
    #pragma unroll
    for (int o = 16; o > 0; o >>= 1) mx = fmaxf(mx, __shfl_xor_sync(0xffffffffu, mx, o));
    if (lane == 0) sred[wid] = mx;
    __syncthreads();
    if (wid == 0) {
        mx = sred[lane & 7];
        #pragma unroll
        for (int o = 4; o > 0; o >>= 1) mx = fmaxf(mx, __shfl_xor_sync(0xffffffffu, mx, o));
        if (lane == 0) sred[0] = mx;
    }
    __syncthreads();
    mx = sred[0];

    v.x = __expf(v.x - mx); v.y = __expf(v.y - mx);
    v.z = __expf(v.z - mx); v.w = __expf(v.w - mx);
    float sum = v.x + v.y + v.z + v.w;
    #pragma unroll
    for (int o = 16; o > 0; o >>= 1) sum += __shfl_xor_sync(0xffffffffu, sum, o);
    if (lane == 0) sred[wid] = sum;
    __syncthreads();
    if (wid == 0) {
        sum = sred[lane & 7];
        #pragma unroll
        for (int o = 4; o > 0; o >>= 1) sum += __shfl_xor_sync(0xffffffffu, sum, o);
        if (lane == 0) sred[0] = sum;
    }
    __syncthreads();
    float inv = 1.f / sred[0];
    uint2 o = make_uint2(packbf(v.x * inv, v.y * inv), packbf(v.z * inv, v.w * inv));
    ((uint2*)orow)[tid] = o;
}

// ---------------- launch ------------------------------------------------------
extern "C" void kernel_launch(void* const* d_in, const int* in_sizes, int n_in,
                              void* d_out, int out_size)
{
    const float* x      = (const float*)d_in[0];
    const float* gn_w   = (const float*)d_in[1];
    const float* gn_b   = (const float*)d_in[2];
    const float* qkv_w  = (const float*)d_in[3];
    const float* qkv_b  = (const float*)d_in[4];
    const float* proj_w = (const float*)d_in[5];
    const float* proj_b = (const float*)d_in[6];
    float* out = (float*)d_out;

    bf16 *xnT, *qT, *kT, *v, *attnbf, *aoutT, *wbf, *pwbf;
    float *attn;
    cudaGetSymbolAddress((void**)&xnT,    g_xnT);
    cudaGetSymbolAddress((void**)&qT,     g_qT);
    cudaGetSymbolAddress((void**)&kT,     g_kT);
    cudaGetSymbolAddress((void**)&v,      g_v);
    cudaGetSymbolAddress((void**)&attn,   g_attn);
    cudaGetSymbolAddress((void**)&attnbf, g_attnbf);
    cudaGetSymbolAddress((void**)&aoutT,  g_aoutT);
    cudaGetSymbolAddress((void**)&wbf,    g_wbf);
    cudaGetSymbolAddress((void**)&pwbf,   g_pwbf);

    const size_t sNC  = (size_t)HW * CH;
    const size_t sCN  = (size_t)CH * HW;
    const size_t sATT = (size_t)HW * HW;
    const float scale = rsqrtf((float)CH);

    // 0) weights -> bf16
    tobf16_kernel<<<(3 * CH * CH / 4 + 255) / 256, 256>>>(qkv_w, wbf, 3 * CH * CH / 4);
    tobf16_kernel<<<(CH * CH / 4 + 255) / 256, 256>>>(proj_w, pwbf, CH * CH / 4);

    // 1) GroupNorm -> xnT bf16 [b][pix][c]
    groupnorm_t_kernel<<<BATCH * NG, 256>>>(x, gn_w, gn_b, xnT);

    // 2) QT[i][co] = xnT[i][c] . Wq[co][c] + qkv_b[co]
    {
        dim3 grid(CH / 128, HW / 128, BATCH);
        gemm_pipe<false, true, false, true><<<grid, 256>>>(
            xnT, wbf, nullptr, qkv_b, nullptr, qT,
            HW, CH, CH, CH, CH, sNC, 0, sNC, 0, 1.0f);
    }
    // 3) KT[j][co]
    {
        dim3 grid(CH / 128, HW / 128, BATCH);
        gemm_pipe<false, true, false, true><<<grid, 256>>>(
            xnT, wbf + (size_t)CH * CH, nullptr, qkv_b + CH, nullptr, kT,
            HW, CH, CH, CH, CH, sNC, 0, sNC, 0, 1.0f);
    }
    // 4) V[co][j] = Wv[co][c] . xnT[j][c] + qkv_b[2CH+co]
    {
        dim3 grid(HW / 128, CH / 128, BATCH);
        gemm_pipe<true, false, false, true><<<grid, 256>>>(
            wbf + (size_t)2 * CH * CH, xnT, qkv_b + 2 * CH, nullptr, nullptr, v,
            CH, HW, CH, CH, CH, 0, sNC, sCN, 0, 1.0f);
    }
    // 5) S[i][j] = scale * QT[i][c] . KT[j][c]   (fp32 out)
    {
        dim3 grid(HW / 128, HW / 128, BATCH);
        gemm_pipe<false, false, false, false><<<grid, 256>>>(
            qT, kT, nullptr, nullptr, nullptr, attn,
            HW, HW, CH, CH, CH, sNC, sNC, sATT, 0, scale);
    }
    // 6) softmax rows -> bf16
    softmax_kernel<<<BATCH * HW, 256>>>(attn, attnbf);

    // 7) aoutT[i][c] = attnbf[i][j] . V[c][j]
    {
        dim3 grid(CH / 128, HW / 128, BATCH);
        gemm_pipe<false, false, false, true><<<grid, 256>>>(
            attnbf, v, nullptr, nullptr, nullptr, aoutT,
            HW, CH, HW, HW, HW, sATT, sCN, sNC, 0, 1.0f);
    }
    // 8) out[co][pix] = P[co][c] . aoutT[pix][c] + proj_b[co] + x  (fp32 out)
    {
        dim3 grid(HW / 128, CH / 128, BATCH);
        gemm_pipe<true, false, true, false><<<grid, 256>>>(
            pwbf, aoutT, proj_b, nullptr, x, out,
            CH, HW, CH, CH, CH, 0, sNC, sCN, sCN, 1.0f);
    }
}